// round 11
// baseline (speedup 1.0000x reference)
#include <cuda_runtime.h>
#include <cuda_bf16.h>
#include <cstdint>

#define Bq 4
#define Lq 4096
#define Sq 4096
#define DM 1024
#define NH 16
#define DKq 64
#define SK 40
#define NT 40
#define FSCALE 0.125f
#define NHT (NH * NT)
#define KSPL 4
#define NCHK 16

// GEMM tiling
#define BKg 32
#define ASTR 40
#define TILE_B (128 * ASTR * 2)
#define STAGE_B (4 * TILE_B)
#define SMEM_MMA (2 * STAGE_B)

// ---------------- scratch ----------------------------------------------------
__device__ float    g_c2[Bq*NH*SK];
__device__ float    g_ks[Bq*NH*SK*DKq];
__device__ float    g_QKs[(size_t)Bq*Lq*NHT];
__device__ float    g_Mv[Bq*NH*Lq];
__device__ int      g_Mtop[Bq*NH*NT];
__device__ float    g_cand_v[Bq*NH*NCHK*NT];
__device__ int      g_cand_i[Bq*NH*NCHK*NT];
__device__ float    g_Qred[(size_t)Bq*NH*NT*DKq];
__device__ float    g_ctx[(size_t)Bq*NH*NT*DKq];
__device__ unsigned g_mask[Bq*Lq];
__device__ int      g_tslot[(size_t)Bq*Lq*NH];
__device__ float    g_S[(size_t)Bq*NHT*Sq];
__device__ float    g_Yp[(size_t)KSPL*Bq*NHT*DM];
__device__ float    g_WoT[(size_t)DM*DM];
__device__ float    g_zb[4096];       // stays zero

__device__ __nv_bfloat16 g_qh[(size_t)Bq*Lq*DM],  g_ql[(size_t)Bq*Lq*DM];
__device__ __nv_bfloat16 g_kh[(size_t)Bq*Sq*DM],  g_kl[(size_t)Bq*Sq*DM];
__device__ __nv_bfloat16 g_vTh[(size_t)Bq*DM*Sq], g_vTl[(size_t)Bq*DM*Sq];
__device__ __nv_bfloat16 g_w2h[(size_t)Bq*NH*SK*DM], g_w2l[(size_t)Bq*NH*SK*DM];
__device__ __nv_bfloat16 g_qwh[(size_t)Bq*NHT*DM], g_qwl[(size_t)Bq*NHT*DM];
__device__ __nv_bfloat16 g_Ph[(size_t)Bq*NHT*Sq], g_Pl[(size_t)Bq*NHT*Sq];

// ---------------- helpers ----------------------------------------------------
__device__ __forceinline__ uint32_t smem_u32(const void* p) {
    uint32_t a;
    asm("{ .reg .u64 t; cvta.to.shared.u64 t, %1; cvt.u32.u64 %0, t; }" : "=r"(a) : "l"(p));
    return a;
}
__device__ __forceinline__ void cp16(uint32_t sa, const void* gp) {
    asm volatile("cp.async.cg.shared.global [%0], [%1], 16;" :: "r"(sa), "l"(gp) : "memory");
}
#define LDMX4(r, a) \
    asm volatile("ldmatrix.sync.aligned.m8n8.x4.shared.b16 {%0,%1,%2,%3}, [%4];" \
        : "=r"((r)[0]), "=r"((r)[1]), "=r"((r)[2]), "=r"((r)[3]) : "r"(a))
__device__ __forceinline__ void mma_bf16(float* d, const uint32_t* a, const uint32_t* b) {
    asm volatile(
        "mma.sync.aligned.m16n8k16.row.col.f32.bf16.bf16.f32 "
        "{%0,%1,%2,%3}, {%4,%5,%6,%7}, {%8,%9}, {%0,%1,%2,%3};"
        : "+f"(d[0]), "+f"(d[1]), "+f"(d[2]), "+f"(d[3])
        : "r"(a[0]), "r"(a[1]), "r"(a[2]), "r"(a[3]), "r"(b[0]), "r"(b[1]));
}
__device__ __forceinline__ void split2(float v, __nv_bfloat16* hp, __nv_bfloat16* lp) {
    __nv_bfloat16 hb = __float2bfloat16_rn(v);
    *hp = hb;
    *lp = __float2bfloat16_rn(v - __bfloat162float(hb));
}

// ---------------- small kernels ---------------------------------------------
__global__ void reset_mask_kernel() {
    int i = blockIdx.x * 256 + threadIdx.x;
    if (i < Bq * Lq) g_mask[i] = 0u;
}

// fused split of queries (z=0) and keys (z=1)
__global__ __launch_bounds__(256) void splitqk_kernel(
    const float4* __restrict__ q, const float4* __restrict__ k,
    uint2* __restrict__ qh, uint2* __restrict__ ql,
    uint2* __restrict__ kh, uint2* __restrict__ kl, int n4)
{
    int i = blockIdx.x * 256 + threadIdx.x;
    if (i >= n4) return;
    const float4* x = blockIdx.y ? k : q;
    uint2* hi = blockIdx.y ? kh : qh;
    uint2* lo = blockIdx.y ? kl : ql;
    float4 v = x[i];
    float vv[4] = {v.x, v.y, v.z, v.w};
    unsigned h[4], l[4];
#pragma unroll
    for (int j = 0; j < 4; j++) {
        __nv_bfloat16 hb = __float2bfloat16_rn(vv[j]);
        float r = vv[j] - __bfloat162float(hb);
        h[j] = __bfloat16_as_ushort(hb);
        l[j] = __bfloat16_as_ushort(__float2bfloat16_rn(r));
    }
    hi[i] = make_uint2(h[0] | (h[1] << 16), h[2] | (h[3] << 16));
    lo[i] = make_uint2(l[0] | (l[1] << 16), l[2] | (l[3] << 16));
}

__global__ __launch_bounds__(256) void splitT_kernel(
    const float* __restrict__ x, __nv_bfloat16* __restrict__ hiT,
    __nv_bfloat16* __restrict__ loT)
{
    __shared__ float t[32][33];
    int b = blockIdx.z;
    int m0 = blockIdx.x * 32, s0 = blockIdx.y * 32;
    int tx = threadIdx.x & 31, ty = threadIdx.x >> 5;
#pragma unroll
    for (int i = 0; i < 4; i++)
        t[ty + i * 8][tx] = x[((size_t)b * Sq + s0 + ty + i * 8) * DM + m0 + tx];
    __syncthreads();
#pragma unroll
    for (int i = 0; i < 4; i++) {
        float v = t[tx][ty + i * 8];
        size_t o = ((size_t)b * DM + m0 + ty + i * 8) * Sq + s0 + tx;
        __nv_bfloat16 hb = __float2bfloat16_rn(v);
        hiT[o] = hb;
        loT[o] = __float2bfloat16_rn(v - __bfloat162float(hb));
    }
}

__global__ __launch_bounds__(256) void woT_kernel(const float* __restrict__ Wo) {
    __shared__ float t[32][33];
    int m0 = blockIdx.x * 32, k0 = blockIdx.y * 32;
    int tx = threadIdx.x & 31, ty = threadIdx.x >> 5;
#pragma unroll
    for (int i = 0; i < 4; i++)
        t[ty + i * 8][tx] = Wo[(size_t)(m0 + ty + i * 8) * DM + k0 + tx];
    __syncthreads();
#pragma unroll
    for (int i = 0; i < 4; i++)
        g_WoT[(size_t)(k0 + ty + i * 8) * DM + m0 + tx] = t[tx][ty + i * 8];
}

// ---------------- HMMA split-bf16 GEMM (ldmatrix fragments) -----------------
__device__ __forceinline__ void load_stage_mma(
    uint32_t sbase, int st,
    const __nv_bfloat16* Ah, const __nv_bfloat16* Al,
    const __nv_bfloat16* Wh, const __nv_bfloat16* Wl, int k0, int ldk, int tid)
{
    uint32_t base = sbase + st * STAGE_B;
    const __nv_bfloat16* srcs[4] = {Ah + k0, Al + k0, Wh + k0, Wl + k0};
#pragma unroll
    for (int t = 0; t < 4; t++) {
        const __nv_bfloat16* g = srcs[t];
        uint32_t tb = base + t * TILE_B;
#pragma unroll
        for (int i = 0; i < 2; i++) {
            int id = tid + i * 256;
            int row = id >> 2, ch = id & 3;
            cp16(tb + row * (ASTR * 2) + ch * 16, g + (size_t)row * ldk + ch * 8);
        }
    }
    asm volatile("cp.async.commit_group;" ::: "memory");
}

__global__ __launch_bounds__(256) void gemm_mma_kernel(
    const __nv_bfloat16* __restrict__ Ah, const __nv_bfloat16* __restrict__ Al,
    const __nv_bfloat16* __restrict__ Wh, const __nv_bfloat16* __restrict__ Wl,
    const float* __restrict__ bias, float* __restrict__ C,
    int ldc, int ldk, int nkt, int ksplit,
    size_t aB, size_t wB, size_t bB, size_t cB)
{
    extern __shared__ __align__(16) char smem[];
    int tid = threadIdx.x, wid = tid >> 5, lane = tid & 31;
    int wm = wid & 3, wn = wid >> 2;
    int qr = lane >> 2, qc = lane & 3;
    int z = blockIdx.z;
    int b = z / ksplit, ch = z % ksplit;

    size_t aoff = (size_t)b * aB + (size_t)blockIdx.y * 128 * ldk + (size_t)ch * nkt * BKg;
    size_t woff = (size_t)b * wB + (size_t)blockIdx.x * 128 * ldk + (size_t)ch * nkt * BKg;
    Ah += aoff; Al += aoff; Wh += woff; Wl += woff;
    const float* bias_p = bias + (size_t)b * bB + blockIdx.x * 128;
    float* Cp = C + (size_t)z * cB + (size_t)blockIdx.y * 128 * ldc + blockIdx.x * 128;

    uint32_t sb = smem_u32(smem);

    // ldmatrix lane-address components
    int aRow = lane & 15, aCol = lane >> 4;          // A: 16 rows x 2 col-halves
    int bj = lane & 7, bt = lane >> 3;               // B: 4 tiles of 8 rows

    float acc[2][8][4];
#pragma unroll
    for (int m = 0; m < 2; m++)
#pragma unroll
        for (int f = 0; f < 8; f++)
#pragma unroll
            for (int i = 0; i < 4; i++) acc[m][f][i] = 0.f;

    load_stage_mma(sb, 0, Ah, Al, Wh, Wl, 0, ldk, tid);
    load_stage_mma(sb, 1, Ah, Al, Wh, Wl, BKg, ldk, tid);

    for (int kt = 0; kt < nkt; kt++) {
        asm volatile("cp.async.wait_group 1;" ::: "memory");
        __syncthreads();

        uint32_t stb = sb + (kt & 1) * STAGE_B;
        uint32_t sAh = stb, sAl = stb + TILE_B;
        uint32_t sWh = stb + 2 * TILE_B, sWl = stb + 3 * TILE_B;

#pragma unroll
        for (int kk = 0; kk < BKg; kk += 16) {
            uint32_t ah[2][4], al[2][4];
#pragma unroll
            for (int m = 0; m < 2; m++) {
                int r = wm * 32 + m * 16 + aRow;
                uint32_t off = (uint32_t)((r * ASTR + kk) * 2 + aCol * 16);
                LDMX4(ah[m], sAh + off);
                LDMX4(al[m], sAl + off);
            }
#pragma unroll
            for (int p = 0; p < 4; p++) {
                int f = p * 2 + (bt >> 1);
                int n = wn * 64 + f * 8 + bj;
                uint32_t off = (uint32_t)((n * ASTR + kk) * 2 + (bt & 1) * 16);
                uint32_t wh4[4], wl4[4];
                LDMX4(wh4, sWh + off);
                LDMX4(wl4, sWl + off);
#pragma unroll
                for (int m = 0; m < 2; m++) {
#pragma unroll
                    for (int ff = 0; ff < 2; ff++) {
                        mma_bf16(acc[m][p * 2 + ff], ah[m], wh4 + ff * 2);
                        mma_bf16(acc[m][p * 2 + ff], ah[m], wl4 + ff * 2);
                        mma_bf16(acc[m][p * 2 + ff], al[m], wh4 + ff * 2);
                    }
                }
            }
        }
        __syncthreads();
        if (kt + 2 < nkt)
            load_stage_mma(sb, kt & 1, Ah, Al, Wh, Wl, (kt + 2) * BKg, ldk, tid);
        else
            asm volatile("cp.async.commit_group;" ::: "memory");
    }

#pragma unroll
    for (int m = 0; m < 2; m++) {
        float* Crow0 = Cp + (size_t)(wm * 32 + m * 16 + qr) * ldc;
        float* Crow1 = Crow0 + 8 * ldc;
#pragma unroll
        for (int f = 0; f < 8; f++) {
            int col = wn * 64 + f * 8 + qc * 2;
            float b0 = bias_p[col], b1 = bias_p[col + 1];
            *(float2*)(Crow0 + col) = make_float2(acc[m][f][0] + b0, acc[m][f][1] + b1);
            *(float2*)(Crow1 + col) = make_float2(acc[m][f][2] + b0, acc[m][f][3] + b1);
        }
    }
}

// ---------------- K_sample + c2 ----------------------------------------------
__global__ __launch_bounds__(256) void ksample_kernel(
    const float* __restrict__ keys, const float* __restrict__ Wk,
    const float* __restrict__ bq, const float* __restrict__ bk,
    const int* __restrict__ idx)
{
    int bh = blockIdx.x;
    int b = bh / NH, h = bh % NH;
    __shared__ float ks[SK * DKq];
    __shared__ float kt[SK][65];
    __shared__ float wt[DKq][65];
    int tid = threadIdx.x, lane = tid & 31, grp = tid >> 5;

    float acc[5][2];
#pragma unroll
    for (int k = 0; k < 5; k++) { acc[k][0] = 0.f; acc[k][1] = 0.f; }
    for (int m0 = 0; m0 < DM; m0 += 64) {
        __syncthreads();
        for (int i = tid; i < SK * 64; i += 256) {
            int s = i >> 6, mm = i & 63;
            kt[s][mm] = keys[((size_t)b * Sq + idx[s]) * DM + m0 + mm];
        }
        for (int i = tid; i < DKq * 64; i += 256) {
            int d = i >> 6, mm = i & 63;
            wt[d][mm] = Wk[(size_t)(h * DKq + d) * DM + m0 + mm];
        }
        __syncthreads();
#pragma unroll 8
        for (int mm = 0; mm < 64; mm++) {
            float w0 = wt[lane][mm], w1 = wt[lane + 32][mm];
#pragma unroll
            for (int k = 0; k < 5; k++) {
                float a = kt[grp + k * 8][mm];
                acc[k][0] += a * w0;
                acc[k][1] += a * w1;
            }
        }
    }
    __syncthreads();
#pragma unroll
    for (int k = 0; k < 5; k++) {
        int s = grp + k * 8;
        float v0 = acc[k][0] + bk[h * DKq + lane];
        float v1 = acc[k][1] + bk[h * DKq + lane + 32];
        ks[s * DKq + lane] = v0;      ks[s * DKq + lane + 32] = v1;
        g_ks[(bh * SK + s) * DKq + lane] = v0;
        g_ks[(bh * SK + s) * DKq + lane + 32] = v1;
    }
    __syncthreads();
    if (tid < SK) {
        float c = 0.f;
#pragma unroll
        for (int d = 0; d < DKq; d++) c += bq[h * DKq + d] * ks[tid * DKq + d];
        g_c2[bh * SK + tid] = c;
    }
}

// ---------------- W2 = Wq_h^T @ K_sample (grid 64 x 4) ----------------------
__global__ __launch_bounds__(256) void w2_kernel(const float* __restrict__ Wq) {
    int bh = blockIdx.x;
    int b = bh / NH, h = bh % NH;
    __shared__ float ks[SK * DKq];
    int tid = threadIdx.x;
    for (int i = tid; i < SK * DKq; i += 256) ks[i] = g_ks[bh * SK * DKq + i];
    __syncthreads();
    int n = blockIdx.y * 256 + tid;
    for (int sb = 0; sb < 5; sb++) {
        float a2[8];
#pragma unroll
        for (int s8 = 0; s8 < 8; s8++) a2[s8] = 0.f;
        for (int d = 0; d < DKq; d++) {
            float w = Wq[(size_t)(h * DKq + d) * DM + n];
#pragma unroll
            for (int s8 = 0; s8 < 8; s8++) a2[s8] += w * ks[(sb * 8 + s8) * DKq + d];
        }
#pragma unroll
        for (int s8 = 0; s8 < 8; s8++) {
            size_t o = ((size_t)b * NH * SK + h * SK + sb * 8 + s8) * DM + n;
            split2(a2[s8], &g_w2h[o], &g_w2l[o]);
        }
    }
}

// ---------------- M = max - mean --------------------------------------------
__global__ __launch_bounds__(256) void reduce_m_kernel() {
    int wg = blockIdx.x * 8 + (threadIdx.x >> 5);
    int lane = threadIdx.x & 31;
    int h = wg % NH;
    int bl = wg / NH;
    int b = bl / Lq, l = bl % Lq;
    const float* p = g_QKs + (size_t)bl * NHT + h * SK;
    float v0 = p[lane];
    float v1 = (lane < SK - 32) ? p[32 + lane] : -3.0e38f;
    float mx = fmaxf(v0, v1);
    float sm = v0 + ((lane < SK - 32) ? p[32 + lane] : 0.f);
#pragma unroll
    for (int o = 16; o; o >>= 1) {
        mx = fmaxf(mx, __shfl_xor_sync(~0u, mx, o));
        sm += __shfl_xor_sync(~0u, sm, o);
    }
    if (lane == 0)
        g_Mv[((size_t)b * NH + h) * Lq + l] = mx - sm * (1.0f / SK);
}

// ---------------- top-40 phase A --------------------------------------------
__global__ __launch_bounds__(256) void topkA_kernel() {
    int bh = blockIdx.x, c = blockIdx.y;
    int tid = threadIdx.x, lane = tid & 31, warp = tid >> 5;
    float v = g_Mv[(size_t)bh * Lq + c * 256 + tid];
    int myidx = c * 256 + tid;
    __shared__ float wv[8];
    __shared__ int   wi[8];
    __shared__ float bestv;
    __shared__ int   besti;
    for (int t = 0; t < NT; t++) {
        float mv = v; int mi = myidx;
#pragma unroll
        for (int o = 16; o; o >>= 1) {
            float ov = __shfl_xor_sync(~0u, mv, o);
            int   oi = __shfl_xor_sync(~0u, mi, o);
            if (ov > mv || (ov == mv && oi < mi)) { mv = ov; mi = oi; }
        }
        if (lane == 0) { wv[warp] = mv; wi[warp] = mi; }
        __syncthreads();
        if (warp == 0) {
            float m2 = (lane < 8) ? wv[lane] : -3.4e38f;
            int   i2 = (lane < 8) ? wi[lane] : 0x7fffffff;
#pragma unroll
            for (int o = 4; o; o >>= 1) {
                float ov = __shfl_xor_sync(~0u, m2, o);
                int   oi = __shfl_xor_sync(~0u, i2, o);
                if (ov > m2 || (ov == m2 && oi < i2)) { m2 = ov; i2 = oi; }
            }
            if (lane == 0) { bestv = m2; besti = i2; }
        }
        __syncthreads();
        if (myidx == besti) v = -3.4e38f;
        if (tid == 0) {
            g_cand_v[(bh * NCHK + c) * NT + t] = bestv;
            g_cand_i[(bh * NCHK + c) * NT + t] = besti;
        }
        __syncthreads();
    }
}

// ---------------- top-40 phase B --------------------------------------------
__global__ __launch_bounds__(256) void topkB_kernel() {
    int bh = blockIdx.x;
    int b = bh / NH, h = bh % NH;
    int tid = threadIdx.x, lane = tid & 31, warp = tid >> 5;
    float v[3]; int ix[3];
#pragma unroll
    for (int j = 0; j < 3; j++) {
        int s = tid + j * 256;
        if (s < NCHK * NT) {
            v[j]  = g_cand_v[bh * NCHK * NT + s];
            ix[j] = g_cand_i[bh * NCHK * NT + s];
        } else { v[j] = -3.4e38f; ix[j] = 0x7fffffff; }
    }
    __shared__ float wv[8];
    __shared__ int   wi[8];
    __shared__ float bestv;
    __shared__ int   besti;
    for (int t = 0; t < NT; t++) {
        float mv = v[0]; int mi = ix[0];
#pragma unroll
        for (int j = 1; j < 3; j++)
            if (v[j] > mv || (v[j] == mv && ix[j] < mi)) { mv = v[j]; mi = ix[j]; }
#pragma unroll
        for (int o = 16; o; o >>= 1) {
            float ov = __shfl_xor_sync(~0u, mv, o);
            int   oi = __shfl_xor_sync(~0u, mi, o);
            if (ov > mv || (ov == mv && oi < mi)) { mv = ov; mi = oi; }
        }
        if (lane == 0) { wv[warp] = mv; wi[warp] = mi; }
        __syncthreads();
        if (warp == 0) {
            float m2 = (lane < 8) ? wv[lane] : -3.4e38f;
            int   i2 = (lane < 8) ? wi[lane] : 0x7fffffff;
#pragma unroll
            for (int o = 4; o; o >>= 1) {
                float ov = __shfl_xor_sync(~0u, m2, o);
                int   oi = __shfl_xor_sync(~0u, i2, o);
                if (ov > m2 || (ov == m2 && oi < i2)) { m2 = ov; i2 = oi; }
            }
            if (lane == 0) { bestv = m2; besti = i2; }
        }
        __syncthreads();
#pragma unroll
        for (int j = 0; j < 3; j++)
            if (ix[j] == besti) v[j] = -3.4e38f;
        if (tid == 0) {
            int li = besti;
            g_Mtop[bh * NT + t] = li;
            g_tslot[((size_t)b * Lq + li) * NH + h] = t;
            atomicOr(&g_mask[b * Lq + li], 1u << h);
        }
        __syncthreads();
    }
}

// ---------------- Q_red (exact fp32) ----------------------------------------
__global__ __launch_bounds__(256) void qred_kernel(
    const float* __restrict__ queries, const float* __restrict__ Wq,
    const float* __restrict__ bq)
{
    int gb = blockIdx.x;
    int t = gb % NT; int bh = gb / NT;
    int h = bh % NH; int b = bh / NH;
    int l = g_Mtop[bh * NT + t];
    __shared__ float qrow[DM];
    int tid = threadIdx.x;
    ((float4*)qrow)[tid] = ((const float4*)(queries + ((size_t)b * Lq + l) * DM))[tid];
    __syncthreads();
    int warp = tid >> 5, lane = tid & 31;
#pragma unroll
    for (int p = 0; p < 8; p++) {
        int d = p * 8 + warp;
        const float* wrow = Wq + (size_t)(h * DKq + d) * DM;
        float s = 0.f;
#pragma unroll
        for (int it = 0; it < 8; it++) {
            float4 w4 = *(const float4*)(wrow + it * 128 + lane * 4);
            float4 q4 = *(const float4*)(qrow + it * 128 + lane * 4);
            s += w4.x * q4.x + w4.y * q4.y + w4.z * q4.z + w4.w * q4.w;
        }
#pragma unroll
        for (int o = 16; o; o >>= 1) s += __shfl_xor_sync(~0u, s, o);
        if (lane == 0) g_Qred[(size_t)gb * DKq + d] = s + bq[h * DKq + d];
    }
}

// ---------------- QW = Qred @ Wk_h  (grid 64 x 4) ---------------------------
__global__ __launch_bounds__(256) void qw_kernel(const float* __restrict__ Wk) {
    int bh = blockIdx.x;
    int h = bh % NH;
    __shared__ float qs[NT * DKq];
    int tid = threadIdx.x;
    for (int i = tid; i < NT * DKq; i += 256)
        qs[i] = g_Qred[(size_t)bh * NT * DKq + i];
    __syncthreads();
    int n = blockIdx.y * 256 + tid;
    for (int sb = 0; sb < 5; sb++) {
        float a2[8];
#pragma unroll
        for (int t8 = 0; t8 < 8; t8++) a2[t8] = 0.f;
        for (int d = 0; d < DKq; d++) {
            float w = Wk[(size_t)(h * DKq + d) * DM + n];
#pragma unroll
            for (int t8 = 0; t8 < 8; t8++) a2[t8] += w * qs[(sb * 8 + t8) * DKq + d];
        }
#pragma unroll
        for (int t8 = 0; t8 < 8; t8++) {
            size_t o = ((size_t)bh * NT + sb * 8 + t8) * DM + n;
            split2(a2[t8], &g_qwh[o], &g_qwl[o]);
        }
    }
}

// ---------------- softmax over S rows -> P hi/lo ----------------------------
__global__ __launch_bounds__(256) void softmax_kernel() {
    int r = blockIdx.x;
    const float* Sp = g_S + (size_t)r * Sq;
    int tid = threadIdx.x;
    float v[16];
    float mx = -3.0e38f;
#pragma unroll
    for (int i = 0; i < 16; i++) {
        v[i] = Sp[tid + i * 256] * FSCALE;
        mx = fmaxf(mx, v[i]);
    }
    __shared__ float red[256];
    red[tid] = mx; __syncthreads();
    for (int s = 128; s; s >>= 1) {
        if (tid < s) red[tid] = fmaxf(red[tid], red[tid + s]);
        __syncthreads();
    }
    mx = red[0]; __syncthreads();
    float sm = 0.f;
#pragma unroll
    for (int i = 0; i < 16; i++) { v[i] = expf(v[i] - mx); sm += v[i]; }
    red[tid] = sm; __syncthreads();
    for (int s = 128; s; s >>= 1) {
        if (tid < s) red[tid] += red[tid + s];
        __syncthreads();
    }
    float inv = 1.0f / red[0];
#pragma unroll
    for (int i = 0; i < 16; i++) {
        float p = v[i] * inv;
        size_t o = (size_t)r * Sq + tid + i * 256;
        __nv_bfloat16 hb = __float2bfloat16_rn(p);
        g_Ph[o] = hb;
        g_Pl[o] = __float2bfloat16_rn(p - __bfloat162float(hb));
    }
}

// ---------------- ctx = sum(Yp) @ Wv_h^T + bv -------------------------------
__global__ __launch_bounds__(256) void ctx_kernel(
    const float* __restrict__ Wv, const float* __restrict__ bv)
{
    int gb = blockIdx.x;
    int t = gb % NT; int bh = gb / NT;
    int h = bh % NH; int b = bh / NH;
    int ht = h * NT + t;
    __shared__ float y[DM];
    int tid = threadIdx.x;
    float4 s4 = make_float4(0.f, 0.f, 0.f, 0.f);
#pragma unroll
    for (int c = 0; c < KSPL; c++) {
        float4 a = ((const float4*)(g_Yp + ((size_t)(b * KSPL + c) * NHT + ht) * DM))[tid];
        s4.x += a.x; s4.y += a.y; s4.z += a.z; s4.w += a.w;
    }
    ((float4*)y)[tid] = s4;
    __syncthreads();
    int warp = tid >> 5, lane = tid & 31;
#pragma unroll
    for (int p = 0; p < 8; p++) {
        int d = p * 8 + warp;
        const float* wrow = Wv + (size_t)(h * DKq + d) * DM;
        float s = 0.f;
#pragma unroll
        for (int it = 0; it < 8; it++) {
            float4 w4 = *(const float4*)(wrow + it * 128 + lane * 4);
            float4 q4 = *(const float4*)(y + it * 128 + lane * 4);
            s += w4.x * q4.x + w4.y * q4.y + w4.z * q4.z + w4.w * q4.w;
        }
#pragma unroll
        for (int o = 16; o; o >>= 1) s += __shfl_xor_sync(~0u, s, o);
        if (lane == 0) g_ctx[(size_t)gb * DKq + d] = s + bv[h * DKq + d];
    }
}

// ---------------- sparse output projection ----------------------------------
__global__ __launch_bounds__(256) void out_kernel(
    const float* __restrict__ bo, float* __restrict__ out)
{
    int row = blockIdx.x;
    int b = row / Lq;
    int tid = threadIdx.x;
    unsigned msk = g_mask[row];
    __shared__ float csm[DKq];

    float4 a4 = ((const float4*)bo)[tid];

    if (msk) {
        for (int h = 0; h < NH; h++) {
            if (!((msk >> h) & 1u)) continue;
            int t = g_tslot[(size_t)row * NH + h];
            __syncthreads();
            if (tid < DKq / 4)
                ((float4*)csm)[tid] =
                    ((const float4*)(g_ctx + ((size_t)(b * NH + h) * NT + t) * DKq))[tid];
            __syncthreads();
#pragma unroll 8
            for (int d = 0; d < DKq; d++) {
                float c = csm[d];
                float4 w4 = ((const float4*)(g_WoT + (size_t)(h * DKq + d) * DM))[tid];
                a4.x += c * w4.x; a4.y += c * w4.y;
                a4.z += c * w4.z; a4.w += c * w4.w;
            }
        }
    }
    ((float4*)(out + (size_t)row * DM))[tid] = a4;
}

// ---------------- launch -----------------------------------------------------
extern "C" void kernel_launch(void* const* d_in, const int* in_sizes, int n_in,
                              void* d_out, int out_size)
{
    const float* queries = (const float*)d_in[0];
    const float* keys    = (const float*)d_in[1];
    const float* values  = (const float*)d_in[2];
    const float* Wq      = (const float*)d_in[3];
    const float* bq      = (const float*)d_in[4];
    const float* Wk      = (const float*)d_in[5];
    const float* bk      = (const float*)d_in[6];
    const float* Wv      = (const float*)d_in[7];
    const float* bv      = (const float*)d_in[8];
    const float* Wo      = (const float*)d_in[9];
    const float* bo      = (const float*)d_in[10];
    const int*   idx     = (const int*)d_in[11];
    float* out = (float*)d_out;

    cudaFuncSetAttribute(gemm_mma_kernel,
                         cudaFuncAttributeMaxDynamicSharedMemorySize, SMEM_MMA);

    void *pc2, *pQKs, *pS, *pYp, *pzb;
    void *pqh, *pql, *pkh, *pkl, *pvTh, *pvTl, *pw2h, *pw2l, *pqwh, *pqwl, *pPh, *pPl;
    cudaGetSymbolAddress(&pc2, g_c2);
    cudaGetSymbolAddress(&pQKs, g_QKs);
    cudaGetSymbolAddress(&pS, g_S);
    cudaGetSymbolAddress(&pYp, g_Yp);
    cudaGetSymbolAddress(&pzb, g_zb);
    cudaGetSymbolAddress(&pqh, g_qh);   cudaGetSymbolAddress(&pql, g_ql);
    cudaGetSymbolAddress(&pkh, g_kh);   cudaGetSymbolAddress(&pkl, g_kl);
    cudaGetSymbolAddress(&pvTh, g_vTh); cudaGetSymbolAddress(&pvTl, g_vTl);
    cudaGetSymbolAddress(&pw2h, g_w2h); cudaGetSymbolAddress(&pw2l, g_w2l);
    cudaGetSymbolAddress(&pqwh, g_qwh); cudaGetSymbolAddress(&pqwl, g_qwl);
    cudaGetSymbolAddress(&pPh, g_Ph);   cudaGetSymbolAddress(&pPl, g_Pl);

    // Launch order arranged so the 4th launch is the QKs GEMM (ncu captures #4).
    int nBig = Bq * Lq * DM / 4;
    splitqk_kernel<<<dim3((nBig + 255) / 256, 2), 256>>>(          // 1
        (const float4*)queries, (const float4*)keys,
        (uint2*)pqh, (uint2*)pql, (uint2*)pkh, (uint2*)pkl, nBig);
    ksample_kernel<<<Bq * NH, 256>>>(keys, Wk, bq, bk, idx);       // 2
    w2_kernel<<<dim3(Bq * NH, 4), 256>>>(Wq);                      // 3

    // 4: QKs[b] = queries[b] @ W2[b]^T + c2[b]
    gemm_mma_kernel<<<dim3(NHT / 128, Lq / 128, Bq), 256, SMEM_MMA>>>(
        (const __nv_bfloat16*)pqh, (const __nv_bfloat16*)pql,
        (const __nv_bfloat16*)pw2h, (const __nv_bfloat16*)pw2l,
        (const float*)pc2, (float*)pQKs,
        NHT, DM, DM / BKg, 1,
        (size_t)Lq * DM, (size_t)NHT * DM, (size_t)NHT, (size_t)Lq * NHT);

    reset_mask_kernel<<<(Bq * Lq + 255) / 256, 256>>>();           // 5
    woT_kernel<<<dim3(DM / 32, DM / 32), 256>>>(Wo);               // 6
    splitT_kernel<<<dim3(DM / 32, Sq / 32, Bq), 256>>>(values,     // 7
        (__nv_bfloat16*)pvTh, (__nv_bfloat16*)pvTl);

    reduce_m_kernel<<<(Bq * Lq * NH) / 8, 256>>>();
    topkA_kernel<<<dim3(Bq * NH, NCHK), 256>>>();
    topkB_kernel<<<Bq * NH, 256>>>();
    qred_kernel<<<Bq * NH * NT, 256>>>(queries, Wq, bq);
    qw_kernel<<<dim3(Bq * NH, 4), 256>>>(Wk);

    // S[b] = QW[b] @ keys[b]^T
    gemm_mma_kernel<<<dim3(Sq / 128, NHT / 128, Bq), 256, SMEM_MMA>>>(
        (const __nv_bfloat16*)pqwh, (const __nv_bfloat16*)pqwl,
        (const __nv_bfloat16*)pkh, (const __nv_bfloat16*)pkl,
        (const float*)pzb, (float*)pS,
        Sq, DM, DM / BKg, 1,
        (size_t)NHT * DM, (size_t)Sq * DM, (size_t)0, (size_t)NHT * Sq);

    softmax_kernel<<<Bq * NHT, 256>>>();

    // Y[b] = P[b] @ values[b], split-K=4
    gemm_mma_kernel<<<dim3(DM / 128, NHT / 128, Bq * KSPL), 256, SMEM_MMA>>>(
        (const __nv_bfloat16*)pPh, (const __nv_bfloat16*)pPl,
        (const __nv_bfloat16*)pvTh, (const __nv_bfloat16*)pvTl,
        (const float*)pzb, (float*)pYp,
        DM, Sq, (Sq / KSPL) / BKg, KSPL,
        (size_t)NHT * Sq, (size_t)DM * Sq, (size_t)0, (size_t)NHT * DM);

    ctx_kernel<<<Bq * NH * NT, 256>>>(Wv, bv);
    out_kernel<<<Bq * Lq, 256>>>(bo, out);
}